// round 3
// baseline (speedup 1.0000x reference)
#include <cuda_runtime.h>

#define DIM   4096
#define RANK  32

// ---------------------------------------------------------------------------
// Single fused kernel: one CTA (256 threads) per row of [B*L, D] = 16384 rows.
//   Non-edited rows (16352 CTAs): streaming float4 copy (evict-first hints).
//   Edited rows (32 CTAs): full ReFT edit computed in-CTA:
//     stage x -> smem; 64 warp-reduced dots (x·Wsrc_r, x·Wproj_r);
//     s = relu(src + bias) - proj; out = x + s·Wproj.
//   Edited CTAs overlap with the copy wave -> no serialized prologue.
// ---------------------------------------------------------------------------
__global__ __launch_bounds__(256) void reft_fused_kernel(
    const float* __restrict__ hs,
    const float* __restrict__ Wsrc_p, const float* __restrict__ bsrc_p,
    const float* __restrict__ Wproj_p,
    const float* __restrict__ Wsrc_s, const float* __restrict__ bsrc_s,
    const float* __restrict__ Wproj_s,
    const int* __restrict__ offsets, const int* __restrict__ seqlens,
    float* __restrict__ out)
{
    const int row = blockIdx.x;            // 0..16383
    const int tid = threadIdx.x;
    const long base = (long)row * DIM;
    const float4* x4 = (const float4*)(hs + base);
    float4*       o4 = (float4*)(out + base);

    const int b = row >> 12;
    const int t = row & 4095;
    const int off = offsets[b];
    const int seq = seqlens[b];

    // Classify row (uniform across CTA)
    bool edited = false;
    const float *Wsrc = Wsrc_p, *bias = bsrc_p, *Wproj = Wproj_p;
    if ((unsigned)(t - off) < 4u) {
        edited = true;
    } else if ((unsigned)(t - (off + seq - 4)) < 4u) {
        edited = true;
        Wsrc = Wsrc_s; bias = bsrc_s; Wproj = Wproj_s;
    }

    if (!edited) {
        // plain streaming copy: 1024 float4 / 256 threads = 4 each
        #pragma unroll
        for (int k = 0; k < 4; k++) {
            int i = tid + k * 256;
            __stcs(&o4[i], __ldcs(&x4[i]));
        }
        return;
    }

    // ---------------- edited row ----------------
    __shared__ float4 xs4[DIM / 4];        // 16 KB
    __shared__ float  dots[2 * RANK];
    __shared__ float  s[RANK];

    #pragma unroll
    for (int k = 0; k < 4; k++) {
        int i = tid + k * 256;
        xs4[i] = x4[i];
    }
    __syncthreads();

    // 64 dots: 8 warps x 8 dots, warp-reduced
    const int warp = tid >> 5;
    const int lane = tid & 31;
    #pragma unroll
    for (int k = 0; k < 8; k++) {
        const int di = warp * 8 + k;       // 0..63
        const float4* W4 = (const float4*)((di < RANK)
                               ? (Wsrc  + (long)di * DIM)
                               : (Wproj + (long)(di - RANK) * DIM));
        float acc = 0.f;
        #pragma unroll 8
        for (int i = lane; i < DIM / 4; i += 32) {
            float4 w  = W4[i];
            float4 xv = xs4[i];
            acc += w.x * xv.x + w.y * xv.y + w.z * xv.z + w.w * xv.w;
        }
        #pragma unroll
        for (int o = 16; o > 0; o >>= 1)
            acc += __shfl_xor_sync(0xffffffff, acc, o);
        if (lane == 0) dots[di] = acc;
    }
    __syncthreads();

    if (tid < RANK) {
        float src  = dots[tid] + bias[tid];
        float proj = dots[tid + RANK];
        s[tid] = (src > 0.f ? src : 0.f) - proj;
    }
    __syncthreads();

    // out = x + s . Wproj
    #pragma unroll
    for (int k = 0; k < 4; k++) {
        int i = tid + k * 256;
        float4 acc = xs4[i];
        #pragma unroll
        for (int r = 0; r < RANK; r++) {
            float4 w = ((const float4*)(Wproj + (long)r * DIM))[i];
            float sr = s[r];
            acc.x += sr * w.x;
            acc.y += sr * w.y;
            acc.z += sr * w.z;
            acc.w += sr * w.w;
        }
        o4[i] = acc;
    }
}

extern "C" void kernel_launch(void* const* d_in, const int* in_sizes, int n_in,
                              void* d_out, int out_size) {
    const float* hs      = (const float*)d_in[0];
    const float* Wsrc_p  = (const float*)d_in[1];
    const float* bsrc_p  = (const float*)d_in[2];
    const float* Wproj_p = (const float*)d_in[3];
    const float* Wsrc_s  = (const float*)d_in[4];
    const float* bsrc_s  = (const float*)d_in[5];
    const float* Wproj_s = (const float*)d_in[6];
    const int*   offsets = (const int*)d_in[7];
    const int*   seqlens = (const int*)d_in[8];
    float* out = (float*)d_out;

    const int nrows = out_size / DIM;      // 16384
    reft_fused_kernel<<<nrows, 256>>>(
        hs, Wsrc_p, bsrc_p, Wproj_p, Wsrc_s, bsrc_s, Wproj_s,
        offsets, seqlens, out);
}